// round 5
// baseline (speedup 1.0000x reference)
#include <cuda_runtime.h>
#include <cuda_bf16.h>
#include <cstdint>

// MaxUnpooling2D scatter-add, persistent single-kernel pipeline.
//   updates/mask: [B=16, H=128, W=128, C=64]  -> 16,777,216 elements
//   output:       [B=16, OH=256, OW=256, C=64] -> 67,108,864 floats (268 MB)
// out_idx = (b<<22) | (mask & ~63) | c   (channel comes from the source element)
//
// R5: one persistent kernel, 592 CTAs (4/SM -> guaranteed co-resident),
// phases separated by a hand-rolled grid barrier:
//   phase 0 : zero(batch 0)
//   phase b+1: scatter(batch b) then zero(batch b+1)   [scatter-first per CTA]
//   phase 16: scatter(batch 15)
// Zero(b) completing chip-wide before scatter(b) keeps the atomic targets
// L2-resident (16.7 MB/batch << 126 MB L2); each output byte reaches DRAM once.
// Barrier counter is monotonic within a launch and reset by a tiny prologue
// kernel, so the graph replays deterministically.

static constexpr int B_DIM     = 16;
static constexpr int HWC       = 1 << 20;            // elems per batch
static constexpr int OUT_PER_B = 1 << 22;            // output floats per batch
static constexpr int THREADS   = 256;
static constexpr int NCTAS     = 148 * 4;            // 592, 4 CTAs/SM (always resident)
static constexpr int GSTRIDE   = NCTAS * THREADS;    // 151,552 threads total
static constexpr int SQ_PER_B  = HWC / 4;            // 262,144 quads per batch
static constexpr int ZV_PER_B  = OUT_PER_B / 4;      // 1,048,576 float4 per batch

__device__ unsigned int g_bar;                       // barrier arrival counter

__global__ void reset_bar_kernel() { g_bar = 0u; }

__device__ __forceinline__ void grid_barrier(unsigned target)
{
    __syncthreads();                      // all CTA threads done with phase work
    if (threadIdx.x == 0) {
        __threadfence();                  // publish this CTA's writes (release)
        atomicAdd(&g_bar, 1u);
        while (*(volatile unsigned*)&g_bar < target) { }
        __threadfence();                  // acquire
    }
    __syncthreads();
}

__device__ __forceinline__ void zero_batch(float* ob, int tid)
{
    float4* o4 = (float4*)ob;
    const float4 z = make_float4(0.f, 0.f, 0.f, 0.f);
    #pragma unroll 4
    for (int i = tid; i < ZV_PER_B; i += GSTRIDE)
        o4[i] = z;
}

__device__ __forceinline__ void scatter_batch(const float4* __restrict__ u4,
                                              const int4*   __restrict__ m4,
                                              float* __restrict__ ob,
                                              int tid)
{
    // SQ_PER_B / GSTRIDE = 1.73 -> exactly two strided slots, second partial.
    int i0 = tid;                         // always < SQ_PER_B
    int i1 = tid + GSTRIDE;
    bool p1 = (i1 < SQ_PER_B);
    int c = (tid << 2) & 63;              // same for i1 (GSTRIDE*4 % 64 == 0)

    // Front-batch all wide loads for MLP.
    float4 u0 = __ldg(&u4[i0]);
    int4   m0 = __ldg(&m4[i0]);
    float4 u1; int4 m1;
    if (p1) { u1 = __ldg(&u4[i1]); m1 = __ldg(&m4[i1]); }

    atomicAdd(&ob[(m0.x & ~63) | (c + 0)], u0.x);
    atomicAdd(&ob[(m0.y & ~63) | (c + 1)], u0.y);
    atomicAdd(&ob[(m0.z & ~63) | (c + 2)], u0.z);
    atomicAdd(&ob[(m0.w & ~63) | (c + 3)], u0.w);
    if (p1) {
        atomicAdd(&ob[(m1.x & ~63) | (c + 0)], u1.x);
        atomicAdd(&ob[(m1.y & ~63) | (c + 1)], u1.y);
        atomicAdd(&ob[(m1.z & ~63) | (c + 2)], u1.z);
        atomicAdd(&ob[(m1.w & ~63) | (c + 3)], u1.w);
    }
}

__global__ void __launch_bounds__(THREADS)
unpool_persistent_kernel(const float4* __restrict__ upd4,
                         const int4*   __restrict__ msk4,
                         float* __restrict__ out)
{
    const int tid = blockIdx.x * THREADS + threadIdx.x;

    // Phase 0: zero batch 0.
    zero_batch(out, tid);
    grid_barrier(NCTAS);

    for (int b = 0; b < B_DIM; b++) {
        // Scatter batch b (its region was zeroed in the previous phase -> L2 hot).
        scatter_batch(upd4 + (size_t)b * SQ_PER_B,
                      msk4 + (size_t)b * SQ_PER_B,
                      out  + (size_t)b * OUT_PER_B,
                      tid);
        // Then zero batch b+1 (independent of the scatter above).
        if (b + 1 < B_DIM) {
            zero_batch(out + (size_t)(b + 1) * OUT_PER_B, tid);
            grid_barrier((unsigned)(b + 2) * NCTAS);
        }
    }
}

extern "C" void kernel_launch(void* const* d_in, const int* in_sizes, int n_in,
                              void* d_out, int out_size)
{
    const float4* upd4 = (const float4*)d_in[0];
    const int4*   msk4 = (const int4*)d_in[1];
    float*        out  = (float*)d_out;

    reset_bar_kernel<<<1, 1>>>();
    unpool_persistent_kernel<<<NCTAS, THREADS>>>(upd4, msk4, out);
}

// round 6
// speedup vs baseline: 1.6475x; 1.6475x over previous
#include <cuda_runtime.h>
#include <cuda_bf16.h>
#include <cstdint>

// MaxUnpooling2D scatter-add.
//   updates/mask: [B=16, H=128, W=128, C=64]  -> 16,777,216 elements
//   output:       [B=16, OH=256, OW=256, C=64] -> 67,108,864 floats (268 MB)
// out_idx = (b<<22) | (mask & ~63) | c   (channel comes from the source element)
//
// R6: exactly R2's winning recipe (phased zero->scatter, 1 quad/thread scatter,
// 1 float4/thread zero, minimal registers, scatter blocks FIRST in the grid so
// long-latency atomics start early and zero stores backfill), but with
// GROUP=2 batches per kernel to halve launch count (17 -> 9).
// Working set per kernel: 33.5 MB scatter targets + 33.5 MB zero targets,
// both L2-resident (126 MB).

static constexpr int B_DIM      = 16;
static constexpr int GROUP      = 2;
static constexpr int NGROUPS    = B_DIM / GROUP;              // 8
static constexpr int HWC        = 1 << 20;                    // elems per batch
static constexpr int OUT_PER_B  = 1 << 22;                    // out floats per batch

static constexpr int THREADS    = 256;

static constexpr int SQ_PER_B   = HWC / 4;                    // 262,144 quads (1<<18)
static constexpr int SQ_PER_G   = GROUP * SQ_PER_B;           // 524,288 quads
static constexpr int S_BLOCKS   = SQ_PER_G / THREADS;         // 2048

static constexpr int ZV_PER_G   = GROUP * OUT_PER_B / 4;      // 2,097,152 float4
static constexpr int Z_BLOCKS   = ZV_PER_G / THREADS;         // 8192

// ---------------------------------------------------------------------------
// Scatter one group (2 batches). Pointers pre-offset to group start.
// One quad (4 consecutive channels) per thread — minimal registers.
__device__ __forceinline__ void scatter_group(const float4* __restrict__ upd4,
                                              const int4*   __restrict__ msk4,
                                              float* __restrict__ out,
                                              int sblk)
{
    int q = sblk * THREADS + threadIdx.x;   // quad index in group, 0 .. 524,287
    int i = q << 2;                         // element index in group
    int bl = q >> 18;                       // batch within group (SQ_PER_B = 1<<18)
    int c  = i & 63;                        // channel of first lane

    float4 u = __ldg(&upd4[q]);
    int4   m = __ldg(&msk4[q]);

    int base = bl << 22;                    // batch-local output offset

    atomicAdd(&out[base | (m.x & ~63) | (c + 0)], u.x);
    atomicAdd(&out[base | (m.y & ~63) | (c + 1)], u.y);
    atomicAdd(&out[base | (m.z & ~63) | (c + 2)], u.z);
    atomicAdd(&out[base | (m.w & ~63) | (c + 3)], u.w);
}

__device__ __forceinline__ void zero_group(float4* __restrict__ out4, int zblk)
{
    out4[zblk * THREADS + threadIdx.x] = make_float4(0.f, 0.f, 0.f, 0.f);
}

// ---------------------------------------------------------------------------
__global__ void __launch_bounds__(THREADS)
zero_kernel(float4* __restrict__ out4)
{
    zero_group(out4, blockIdx.x);
}

// Fused: scatter group g (blocks [0, S_BLOCKS)) then zero group g+1
// (blocks [S_BLOCKS, S_BLOCKS+Z_BLOCKS)). Scatter-first block order.
__global__ void __launch_bounds__(THREADS)
scatter_zero_kernel(const float4* __restrict__ upd4,
                    const int4*   __restrict__ msk4,
                    float* __restrict__ out_g,
                    float4* __restrict__ out4_next)
{
    int blk = blockIdx.x;
    if (blk < S_BLOCKS) {
        scatter_group(upd4, msk4, out_g, blk);
    } else {
        zero_group(out4_next, blk - S_BLOCKS);
    }
}

__global__ void __launch_bounds__(THREADS)
scatter_kernel(const float4* __restrict__ upd4,
               const int4*   __restrict__ msk4,
               float* __restrict__ out_g)
{
    scatter_group(upd4, msk4, out_g, blockIdx.x);
}

// ---------------------------------------------------------------------------
extern "C" void kernel_launch(void* const* d_in, const int* in_sizes, int n_in,
                              void* d_out, int out_size)
{
    const float4* upd4 = (const float4*)d_in[0];
    const int4*   msk4 = (const int4*)d_in[1];
    float*        out  = (float*)d_out;

    const size_t GRP_QUADS = (size_t)SQ_PER_G;                 // input quads per group
    const size_t GRP_OUT   = (size_t)GROUP * OUT_PER_B;        // output floats per group

    // Prologue: zero group 0.
    zero_kernel<<<Z_BLOCKS, THREADS>>>((float4*)out);

    // Steady state: scatter(g) then zero(g+1), phased by block order.
    for (int g = 0; g < NGROUPS - 1; g++) {
        scatter_zero_kernel<<<S_BLOCKS + Z_BLOCKS, THREADS>>>(
            upd4 + (size_t)g * GRP_QUADS,
            msk4 + (size_t)g * GRP_QUADS,
            out  + (size_t)g * GRP_OUT,
            (float4*)(out + (size_t)(g + 1) * GRP_OUT));
    }

    // Epilogue: scatter last group.
    int g = NGROUPS - 1;
    scatter_kernel<<<S_BLOCKS, THREADS>>>(
        upd4 + (size_t)g * GRP_QUADS,
        msk4 + (size_t)g * GRP_QUADS,
        out  + (size_t)g * GRP_OUT);
}